// round 14
// baseline (speedup 1.0000x reference)
#include <cuda_runtime.h>
#include <cuda_bf16.h>
#include <cuda_fp16.h>
#include <cstdint>
#include <cmath>

// Problem constants
#define NB    4
#define TSEQ  2048
#define CDIM  1024
#define NH    16
#define HS    64
#define BT    (NB*TSEQ)     // 8192 rows
#define NQKV  (3*CDIM)      // 3072
#define CHUNK 128
#define NCHUNK (TSEQ/CHUNK) // 16
#define NBH   (NB*NH)       // 64

// Scratch (device globals: allocation-free rule)
__device__ float g_qkv[(size_t)BT * NQKV];                 // 100.7 MB
__device__ float g_G[(size_t)NBH * NCHUNK * HS * HS];      // 16.8 MB
__device__ float g_Gp[(size_t)NBH * NCHUNK * HS * HS];     // 16.8 MB prefix sums
__device__ float g_logits[(size_t)BT * CDIM];              // 33.6 MB
__device__ __half g_Ah[2ULL * BT * CDIM];                  // 33.6 MB: x split, [t][row][k]
__device__ __half g_Bh[2ULL * NQKV * CDIM];                // 12.6 MB: (64*w) split, transposed [t][n][k]

// ======================= PTX helpers (base sm_80+ ISA only) =======================
__device__ __forceinline__ uint32_t smem_u32(const void* p) {
    uint32_t a;
    asm("{ .reg .u64 t; cvta.to.shared.u64 t, %1; cvt.u32.u64 %0, t; }" : "=r"(a) : "l"(p));
    return a;
}
#define CP_ASYNC16(dst, src) \
    asm volatile("cp.async.cg.shared.global [%0], [%1], 16;" :: "r"(dst), "l"(src) : "memory")
#define CP_COMMIT() asm volatile("cp.async.commit_group;" ::: "memory")
#define CP_WAIT(n)  asm volatile("cp.async.wait_group %0;" :: "n"(n) : "memory")

#define LDSM4(a0,a1,a2,a3,addr) \
    asm volatile("ldmatrix.sync.aligned.m8n8.x4.shared.b16 {%0,%1,%2,%3}, [%4];" \
                 : "=r"(a0),"=r"(a1),"=r"(a2),"=r"(a3) : "r"(addr))
#define LDSM2(b0,b1,addr) \
    asm volatile("ldmatrix.sync.aligned.m8n8.x2.shared.b16 {%0,%1}, [%2];" \
                 : "=r"(b0),"=r"(b1) : "r"(addr))
#define LDSM2T(b0,b1,addr) \
    asm volatile("ldmatrix.sync.aligned.m8n8.x2.trans.shared.b16 {%0,%1}, [%2];" \
                 : "=r"(b0),"=r"(b1) : "r"(addr))
#define MMA16816F16(d,a,b) \
    asm volatile("mma.sync.aligned.m16n8k16.row.col.f32.f16.f16.f32 " \
                 "{%0,%1,%2,%3},{%4,%5,%6,%7},{%8,%9},{%0,%1,%2,%3};" \
                 : "+f"((d)[0]),"+f"((d)[1]),"+f"((d)[2]),"+f"((d)[3]) \
                 : "r"((a)[0]),"r"((a)[1]),"r"((a)[2]),"r"((a)[3]),"r"((b)[0]),"r"((b)[1]))

// ======================= fp16 2-term split =======================
__device__ __forceinline__ void split2h(float v, unsigned short& u0, unsigned short& u1) {
    __half h0 = __float2half_rn(v);
    float r = v - __half2float(h0);
    __half h1 = __float2half_rn(r);
    u0 = __half_as_ushort(h0);
    u1 = __half_as_ushort(h1);
}
__device__ __forceinline__ uint32_t pack2(unsigned short lo, unsigned short hi) {
    return (uint32_t)lo | ((uint32_t)hi << 16);
}

// ======================= Kernel 0a: split x into 2 fp16 terms =======================
__global__ __launch_bounds__(256) void split_x(const float* __restrict__ in) {
    size_t i = ((size_t)blockIdx.x * 256 + threadIdx.x) * 4;
    float4 v = *(const float4*)(in + i);
    ushort4 o0, o1;
    split2h(v.x, o0.x, o1.x);
    split2h(v.y, o0.y, o1.y);
    split2h(v.z, o0.z, o1.z);
    split2h(v.w, o0.w, o1.w);
    unsigned short* p = (unsigned short*)g_Ah;
    const size_t S = (size_t)BT * CDIM;
    *(ushort4*)(p + i) = o0;
    *(ushort4*)(p + S + i) = o1;
}

// ======================= Kernel 0b: split + transpose (64*w_qkv) =======================
__global__ __launch_bounds__(256) void split_wT(const float* __restrict__ w) {
    __shared__ unsigned short t0[32][33], t1[32][33];
    const int n0 = blockIdx.x * 32, k0 = blockIdx.y * 32;
    const int tx = threadIdx.x & 31, ty = threadIdx.x >> 5;
#pragma unroll
    for (int j = 0; j < 4; j++) {
        int k = ty + j * 8;
        float v = w[(size_t)(k0 + k) * NQKV + n0 + tx] * 64.0f;
        split2h(v, t0[k][tx], t1[k][tx]);
    }
    __syncthreads();
    unsigned short* p = (unsigned short*)g_Bh;
    const size_t S = (size_t)NQKV * CDIM;
#pragma unroll
    for (int j = 0; j < 4; j++) {
        int n = ty + j * 8;
        size_t o = (size_t)(n0 + n) * CDIM + k0 + tx;
        p[o]     = t0[tx][n];
        p[S + o] = t1[tx][n];
    }
}

// ======================= Kernel 1: fused 3-pass HMMA GEMM =======================
// BK=32, unpadded XOR-swizzled tiles (8KB), 3-stage pipeline, 1 barrier/chunk.
// B fragments via paired ldmatrix.x4 (16-row groups). Order == R13 (bit-identical).
#define BK 32
#define TILE_BYTES (128 * 64)                  // 8192 (128 rows x 64B)
#define STAGE_BYTES (4 * TILE_BYTES)           // 32768 (A0,A1,B0,B1)
#define NSTAGE 3
#define KCHUNKS (CDIM / BK)                    // 32

// swizzled byte offset of 16B chunk (row r, chunk c2 in 0..3) within a tile
__device__ __forceinline__ uint32_t swz(int r, int c2) {
    return (uint32_t)(r * 64 + ((c2 ^ ((r >> 1) & 3)) << 4));
}

__global__ __launch_bounds__(256, 2) void gemm_hmma(int bn0) {
    extern __shared__ __align__(16) unsigned char smem[];

    const int tid  = threadIdx.x;
    const int wid  = tid >> 5, lane = tid & 31;
    const int wm   = wid >> 2;
    const int wn   = wid & 3;
    const int bn   = bn0 + blockIdx.x, bm = blockIdx.y;

    const size_t SA = (size_t)BT * CDIM, SB = (size_t)NQKV * CDIM;
    const size_t arow0 = (size_t)(bm * 128) * CDIM;
    const size_t brow0 = (size_t)(bn * 128) * CDIM;

    const uint32_t sbase = smem_u32(smem);

    const int aR = lane & 15;                 // ldmatrix x4 row lane
    const int aCk = lane >> 4;                // ldmatrix x4 chunk sel (0/1)

    float acc[4][4][4];
#pragma unroll
    for (int i = 0; i < 4; i++)
#pragma unroll
        for (int j = 0; j < 4; j++)
#pragma unroll
            for (int k = 0; k < 4; k++) acc[i][j][k] = 0.f;

    // gmem->smem: 512 chunks/tile; thread handles chunk ids tid and tid+256
    const int r0 = tid >> 2, c20 = tid & 3;   // rows 0..63
    const uint32_t so0 = swz(r0, c20);
    const uint32_t so1 = swz(r0 + 64, c20);
    const size_t go0 = (size_t)r0 * CDIM + c20 * 8;
    const size_t go1 = (size_t)(r0 + 64) * CDIM + c20 * 8;

    auto prefetch = [&](int chunk) {
        if (chunk < KCHUNKS) {
            const int s = chunk % NSTAGE;
            const size_t ko = (size_t)chunk * BK;
            const uint32_t st = sbase + s * STAGE_BYTES;
            const __half* A0 = g_Ah + arow0 + ko;
            const __half* B0 = g_Bh + brow0 + ko;
            CP_ASYNC16(st + so0,                  A0 + go0);
            CP_ASYNC16(st + so1,                  A0 + go1);
            CP_ASYNC16(st + TILE_BYTES + so0,     A0 + SA + go0);
            CP_ASYNC16(st + TILE_BYTES + so1,     A0 + SA + go1);
            CP_ASYNC16(st + 2 * TILE_BYTES + so0, B0 + go0);
            CP_ASYNC16(st + 2 * TILE_BYTES + so1, B0 + go1);
            CP_ASYNC16(st + 3 * TILE_BYTES + so0, B0 + SB + go0);
            CP_ASYNC16(st + 3 * TILE_BYTES + so1, B0 + SB + go1);
        }
        CP_COMMIT();
    };

    prefetch(0); prefetch(1);

    for (int i = 0; i < KCHUNKS; i++) {
        CP_WAIT(1);
        __syncthreads();
        // stage (i+2)%3 == (i-1)%3 : finished last iteration -> safe post-barrier
        prefetch(i + 2);

        const uint32_t st = sbase + (i % NSTAGE) * STAGE_BYTES;
        const uint32_t sA0 = st;
        const uint32_t sA1 = st + TILE_BYTES;
        const uint32_t sB0 = st + 2 * TILE_BYTES;
        const uint32_t sB1 = st + 3 * TILE_BYTES;

#pragma unroll
        for (int ks = 0; ks < 2; ks++) {
            const int kc = ks * 2;            // base chunk index
            uint32_t af[4][4], bq0[2][4], bq1[2][4];
#pragma unroll
            for (int mi = 0; mi < 4; mi++) {
                int r = wm * 64 + mi * 16 + aR;
                LDSM4(af[mi][0], af[mi][1], af[mi][2], af[mi][3], sA0 + swz(r, kc + aCk));
            }
            // B0 fragments: 2 x4 loads covering n rows wn*32..wn*32+31
#pragma unroll
            for (int q = 0; q < 2; q++) {
                int r = wn * 32 + q * 16 + aR;
                LDSM4(bq0[q][0], bq0[q][1], bq0[q][2], bq0[q][3], sB0 + swz(r, kc + aCk));
            }
            // a0 * b0
#pragma unroll
            for (int mi = 0; mi < 4; mi++)
#pragma unroll
                for (int q = 0; q < 2; q++) {
                    uint32_t blo[2] = { bq0[q][0], bq0[q][2] };   // n rows 0-7 of group
                    uint32_t bhi[2] = { bq0[q][1], bq0[q][3] };   // n rows 8-15
                    MMA16816F16(acc[mi][q * 2],     af[mi], blo);
                    MMA16816F16(acc[mi][q * 2 + 1], af[mi], bhi);
                }
            // a0 * b1
#pragma unroll
            for (int q = 0; q < 2; q++) {
                int r = wn * 32 + q * 16 + aR;
                LDSM4(bq1[q][0], bq1[q][1], bq1[q][2], bq1[q][3], sB1 + swz(r, kc + aCk));
            }
#pragma unroll
            for (int mi = 0; mi < 4; mi++)
#pragma unroll
                for (int q = 0; q < 2; q++) {
                    uint32_t blo[2] = { bq1[q][0], bq1[q][2] };
                    uint32_t bhi[2] = { bq1[q][1], bq1[q][3] };
                    MMA16816F16(acc[mi][q * 2],     af[mi], blo);
                    MMA16816F16(acc[mi][q * 2 + 1], af[mi], bhi);
                }
            // a1 * b0 (reuse af registers)
#pragma unroll
            for (int mi = 0; mi < 4; mi++) {
                int r = wm * 64 + mi * 16 + aR;
                LDSM4(af[mi][0], af[mi][1], af[mi][2], af[mi][3], sA1 + swz(r, kc + aCk));
            }
#pragma unroll
            for (int mi = 0; mi < 4; mi++)
#pragma unroll
                for (int q = 0; q < 2; q++) {
                    uint32_t blo[2] = { bq0[q][0], bq0[q][2] };
                    uint32_t bhi[2] = { bq0[q][1], bq0[q][3] };
                    MMA16816F16(acc[mi][q * 2],     af[mi], blo);
                    MMA16816F16(acc[mi][q * 2 + 1], af[mi], bhi);
                }
        }
    }

    const int g = lane >> 2, t2 = (lane & 3) * 2;
    const float inv64 = 0.015625f;
    float* Cb = g_qkv + (size_t)(bm * 128 + wm * 64) * NQKV + bn * 128 + wn * 32;
#pragma unroll
    for (int mi = 0; mi < 4; mi++) {
#pragma unroll
        for (int nj = 0; nj < 4; nj++) {
            float* p0 = Cb + (size_t)(mi * 16 + g) * NQKV + nj * 8 + t2;
            *(float2*)p0 = make_float2(acc[mi][nj][0] * inv64, acc[mi][nj][1] * inv64);
            *(float2*)(p0 + 8 * NQKV) = make_float2(acc[mi][nj][2] * inv64, acc[mi][nj][3] * inv64);
        }
    }
}

// ======================= Kernel 2: per-chunk K^T V (64x64, fp32, float4 loads) =======================
__global__ __launch_bounds__(256) void kv_outer() {
    const int bidx = blockIdx.x;
    const int bh = bidx >> 4, ci = bidx & 15;
    const int b = bh >> 4, h = bh & 15;
    const int t0 = ci * CHUNK;
    __shared__ float Ks[64][68];
    __shared__ float Vs[64][68];
    const int tid = threadIdx.x;
    const int ty = tid >> 4, tx = tid & 15;
    float acc[4][4] = {};
    const float* base = g_qkv + (size_t)(b * TSEQ + t0) * NQKV + h * HS;

    for (int half = 0; half < 2; half++) {
        __syncthreads();
        for (int idx = tid; idx < 64 * 16; idx += 256) {
            int r = idx >> 4, c4 = (idx & 15) * 4;
            const float* p = base + (size_t)(half * 64 + r) * NQKV + c4;
            *(float4*)&Ks[r][c4] = *(const float4*)(p + CDIM);
            *(float4*)&Vs[r][c4] = *(const float4*)(p + 2 * CDIM);
        }
        __syncthreads();
#pragma unroll 4
        for (int k = 0; k < 64; k++) {
            float rk[4], rv[4];
#pragma unroll
            for (int i = 0; i < 4; i++) rk[i] = Ks[k][i * 16 + ty];
#pragma unroll
            for (int j = 0; j < 4; j++) rv[j] = Vs[k][j * 16 + tx];
#pragma unroll
            for (int i = 0; i < 4; i++)
#pragma unroll
                for (int j = 0; j < 4; j++) acc[i][j] += rk[i] * rv[j];
        }
    }
    float* g = g_G + (size_t)bidx * (HS * HS);
#pragma unroll
    for (int i = 0; i < 4; i++)
#pragma unroll
        for (int j = 0; j < 4; j++)
            g[(i * 16 + ty) * HS + (j * 16 + tx)] = acc[i][j];
}

// ======================= Kernel 2b: prefix sums over G =======================
__global__ __launch_bounds__(256) void prefix_G() {
    const int bh = blockIdx.x;
    const float* Gb = g_G + (size_t)bh * NCHUNK * (HS * HS);
    float* Gp = g_Gp + (size_t)bh * NCHUNK * (HS * HS);
    for (int e = threadIdx.x * 4; e < HS * HS; e += 256 * 4) {
        float4 run = make_float4(0.f, 0.f, 0.f, 0.f);
#pragma unroll
        for (int j = 0; j < NCHUNK; j++) {
            *(float4*)(Gp + (size_t)j * (HS * HS) + e) = run;
            float4 gv = *(const float4*)(Gb + (size_t)j * (HS * HS) + e);
            run.x += gv.x; run.y += gv.y; run.z += gv.z; run.w += gv.w;
        }
    }
}

// ======================= Kernel 3: fused HMMA attention =======================
#define AST 72
#define SST 136
#define OFF_QH0 0
#define OFF_QH1 18432
#define OFF_KH0 36864
#define OFF_KH1 55296
#define OFF_VH0 73728
#define OFF_VH1 92160
#define OFF_MH0 110592
#define OFF_MH1 119808
#define OFF_SH0 129024
#define OFF_SH1 163840
#define ATTN_SMEM_BYTES 198656

__global__ __launch_bounds__(256) void attn_hmma() {
    extern __shared__ __align__(16) unsigned char sm[];
    const uint32_t sb = smem_u32(sm);

    const int bidx = blockIdx.x;
    const int bh = bidx >> 4, ci = bidx & 15;
    const int b = bh >> 4, h = bh & 15;
    const int tid = threadIdx.x, wid = tid >> 5, lane = tid & 31;
    const float* base = g_qkv + (size_t)(b * TSEQ + ci * CHUNK) * NQKV + h * HS;

    {
        unsigned short* QH0 = (unsigned short*)(sm + OFF_QH0);
        unsigned short* QH1 = (unsigned short*)(sm + OFF_QH1);
        unsigned short* KH0 = (unsigned short*)(sm + OFF_KH0);
        unsigned short* KH1 = (unsigned short*)(sm + OFF_KH1);
        unsigned short* VH0 = (unsigned short*)(sm + OFF_VH0);
        unsigned short* VH1 = (unsigned short*)(sm + OFF_VH1);
        for (int idx = tid; idx < 128 * 16; idx += 256) {
            int r = idx >> 4, c4 = (idx & 15) * 4;
            const float* p = base + (size_t)r * NQKV + c4;
            float4 q = *(const float4*)(p);
            float4 k = *(const float4*)(p + CDIM);
            float4 v = *(const float4*)(p + 2 * CDIM);
            int o = r * AST + c4;
            unsigned short a0, a1, b0, b1, e0, e1, f0, f1;
            split2h(q.x, a0, a1); split2h(q.y, b0, b1); split2h(q.z, e0, e1); split2h(q.w, f0, f1);
            *(uint2*)(QH0 + o) = make_uint2(pack2(a0, b0), pack2(e0, f0));
            *(uint2*)(QH1 + o) = make_uint2(pack2(a1, b1), pack2(e1, f1));
            split2h(k.x, a0, a1); split2h(k.y, b0, b1); split2h(k.z, e0, e1); split2h(k.w, f0, f1);
            *(uint2*)(KH0 + o) = make_uint2(pack2(a0, b0), pack2(e0, f0));
            *(uint2*)(KH1 + o) = make_uint2(pack2(a1, b1), pack2(e1, f1));
            split2h(v.x, a0, a1); split2h(v.y, b0, b1); split2h(v.z, e0, e1); split2h(v.w, f0, f1);
            *(uint2*)(VH0 + o) = make_uint2(pack2(a0, b0), pack2(e0, f0));
            *(uint2*)(VH1 + o) = make_uint2(pack2(a1, b1), pack2(e1, f1));
        }
        unsigned short* MH0 = (unsigned short*)(sm + OFF_MH0);
        unsigned short* MH1 = (unsigned short*)(sm + OFF_MH1);
        const float* Mp = g_Gp + ((size_t)bh * NCHUNK + ci) * (HS * HS);
        for (int idx = tid; idx < 64 * 16; idx += 256) {
            int r = idx >> 4, c4 = (idx & 15) * 4;
            float4 mv = *(const float4*)(Mp + r * HS + c4);
            unsigned short a0, a1, b0, b1, e0, e1, f0, f1;
            split2h(mv.x * 0.125f, a0, a1);
            split2h(mv.y * 0.125f, b0, b1);
            split2h(mv.z * 0.125f, e0, e1);
            split2h(mv.w * 0.125f, f0, f1);
            int o = r * AST + c4;
            *(uint2*)(MH0 + o) = make_uint2(pack2(a0, b0), pack2(e0, f0));
            *(uint2*)(MH1 + o) = make_uint2(pack2(a1, b1), pack2(e1, f1));
        }
    }
    __syncthreads();

    const int aR = lane & 15, aC = (lane >> 4) * 8;
    const int bR = lane & 7,  bC = ((lane >> 3) & 1) * 8;
    const int bRow = lane & 15;
    const int g = lane >> 2, t2 = (lane & 3) * 2;
    const int PA[3] = {0, 0, 1};
    const int PB[3] = {0, 1, 0};
    const uint32_t QHa[2] = { sb + OFF_QH0, sb + OFF_QH1 };
    const uint32_t KHa[2] = { sb + OFF_KH0, sb + OFF_KH1 };
    const uint32_t VHa[2] = { sb + OFF_VH0, sb + OFF_VH1 };
    const uint32_t MHa[2] = { sb + OFF_MH0, sb + OFF_MH1 };
    const uint32_t SHa[2] = { sb + OFF_SH0, sb + OFF_SH1 };

    // phase 1: S = Q K^T (128x128), warp tile 64x32
    {
        const int wm = wid >> 2, wn = wid & 3;
        float acc[4][4][4];
#pragma unroll
        for (int i = 0; i < 4; i++)
#pragma unroll
            for (int j = 0; j < 4; j++)
#pragma unroll
                for (int k = 0; k < 4; k++) acc[i][j][k] = 0.f;

#pragma unroll
        for (int p = 0; p < 3; p++) {
            const uint32_t Ap = QHa[PA[p]], Bp = KHa[PB[p]];
#pragma unroll
            for (int ks = 0; ks < 4; ks++) {
                const int k0 = ks * 16;
                uint32_t af[4][4], bf[4][2];
#pragma unroll
                for (int mi = 0; mi < 4; mi++)
                    LDSM4(af[mi][0], af[mi][1], af[mi][2], af[mi][3],
                          Ap + (uint32_t)((wm * 64 + mi * 16 + aR) * AST + k0 + aC) * 2);
#pragma unroll
                for (int nj = 0; nj < 4; nj++)
                    LDSM2(bf[nj][0], bf[nj][1],
                          Bp + (uint32_t)((wn * 32 + nj * 8 + bR) * AST + k0 + bC) * 2);
#pragma unroll
                for (int mi = 0; mi < 4; mi++)
#pragma unroll
                    for (int nj = 0; nj < 4; nj++)
                        MMA16816F16(acc[mi][nj], af[mi], bf[nj]);
            }
        }
        unsigned short* S0 = (unsigned short*)(sm + OFF_SH0);
        unsigned short* S1 = (unsigned short*)(sm + OFF_SH1);
#pragma unroll
        for (int mi = 0; mi < 4; mi++) {
#pragma unroll
            for (int nj = 0; nj < 4; nj++) {
                const int c0 = (wid & 3) * 32 + nj * 8 + t2;
#pragma unroll
                for (int hh = 0; hh < 2; hh++) {
                    const int r = (wid >> 2) * 64 + mi * 16 + g + hh * 8;
                    float va = (r >= c0)     ? acc[mi][nj][hh * 2]     * 0.125f : 0.f;
                    float vb = (r >= c0 + 1) ? acc[mi][nj][hh * 2 + 1] * 0.125f : 0.f;
                    unsigned short a0, a1, b0, b1;
                    split2h(va, a0, a1);
                    split2h(vb, b0, b1);
                    *(uint32_t*)(S0 + r * SST + c0) = pack2(a0, b0);
                    *(uint32_t*)(S1 + r * SST + c0) = pack2(a1, b1);
                }
            }
        }
    }
    __syncthreads();

    // phase 2: O = [S | Q] @ [V ; M'] (128x64, inner 192), warp tile 32x32
    {
        const int wy = wid >> 1, wx = wid & 1;
        float acc[2][4][4];
#pragma unroll
        for (int i = 0; i < 2; i++)
#pragma unroll
            for (int j = 0; j < 4; j++)
#pragma unroll
                for (int k = 0; k < 4; k++) acc[i][j][k] = 0.f;

#pragma unroll
        for (int p = 0; p < 3; p++) {
            const uint32_t Sa = SHa[PA[p]], Qa = QHa[PA[p]];
            const uint32_t Va = VHa[PB[p]], Ma = MHa[PB[p]];
#pragma unroll
            for (int step = 0; step < 12; step++) {
                const int k0 = step * 16;
                uint32_t af[2][4], bf[4][2];
#pragma unroll
                for (int mi = 0; mi < 2; mi++) {
                    const int row = wy * 32 + mi * 16 + aR;
                    uint32_t addr = (k0 < 128)
                        ? Sa + (uint32_t)(row * SST + k0 + aC) * 2
                        : Qa + (uint32_t)(row * AST + (k0 - 128) + aC) * 2;
                    LDSM4(af[mi][0], af[mi][1], af[mi][2], af[mi][3], addr);
                }
#pragma unroll
                for (int nj = 0; nj < 4; nj++) {
                    const int n0 = wx * 32 + nj * 8;
                    uint32_t addr = (k0 < 128)
                        ? Va + (uint32_t)((k0 + bRow) * AST + n0) * 2
                        : Ma + (uint32_t)((k0 - 128 + bRow) * AST + n0) * 2;
                    LDSM2T(bf[nj][0], bf[nj][1], addr);
                }
#pragma unroll
                for (int mi = 0; mi < 2; mi++)
#pragma unroll
                    for (int nj = 0; nj < 4; nj++)
                        MMA16816F16(acc[mi][nj], af[mi], bf[nj]);
            }
        }
        float* outp = g_logits + (size_t)(b * TSEQ + ci * CHUNK) * CDIM + h * HS;
#pragma unroll
        for (int mi = 0; mi < 2; mi++) {
#pragma unroll
            for (int nj = 0; nj < 4; nj++) {
                const int r = wy * 32 + mi * 16 + g;
                const int c = wx * 32 + nj * 8 + t2;
                *(float2*)(outp + (size_t)r * CDIM + c) =
                    make_float2(acc[mi][nj][0], acc[mi][nj][1]);
                *(float2*)(outp + (size_t)(r + 8) * CDIM + c) =
                    make_float2(acc[mi][nj][2], acc[mi][nj][3]);
            }
        }
    }
}

// ======================= Kernel 4: fused epilogue (float4) =======================
__device__ __forceinline__ float warpSum(float v) {
#pragma unroll
    for (int o = 16; o; o >>= 1) v += __shfl_xor_sync(0xffffffffu, v, o);
    return v;
}
__device__ __forceinline__ float warpMax(float v) {
#pragma unroll
    for (int o = 16; o; o >>= 1) v = fmaxf(v, __shfl_xor_sync(0xffffffffu, v, o));
    return v;
}
__device__ float blockSum(float v, float* sh) {
    int lane = threadIdx.x & 31, w = threadIdx.x >> 5;
    v = warpSum(v);
    if (lane == 0) sh[w] = v;
    __syncthreads();
    if (w == 0) {
        float t = (lane < 8) ? sh[lane] : 0.f;
        t = warpSum(t);
        if (lane == 0) sh[32] = t;
    }
    __syncthreads();
    float r = sh[32];
    __syncthreads();
    return r;
}
__device__ float blockMax(float v, float* sh) {
    int lane = threadIdx.x & 31, w = threadIdx.x >> 5;
    v = warpMax(v);
    if (lane == 0) sh[w] = v;
    __syncthreads();
    if (w == 0) {
        float t = (lane < 8) ? sh[lane] : -3.4e38f;
        t = warpMax(t);
        if (lane == 0) sh[32] = t;
    }
    __syncthreads();
    float r = sh[32];
    __syncthreads();
    return r;
}

__global__ __launch_bounds__(256) void epilogue(const float* __restrict__ x,
                                                const float* __restrict__ noise,
                                                const float* __restrict__ lnw,
                                                float* __restrict__ out,
                                                float LSf, float DENf) {
    __shared__ float sh[33];
    const int row = blockIdx.x;
    const int tid = threadIdx.x;
    const int c0 = tid * 4;
    const float* L = g_logits + (size_t)row * CDIM;

    float4 lv = *(const float4*)(L + c0);
    float l[4] = { lv.x, lv.y, lv.z, lv.w };

    float s = (l[0] + l[1]) + (l[2] + l[3]);
    float mu = blockSum(s, sh) * (1.f / 1024.f);

    float d[4], sq = 0.f;
#pragma unroll
    for (int k = 0; k < 4; k++) { d[k] = l[k] - mu; sq += d[k] * d[k]; }
    float var = blockSum(sq, sh) * (1.f / 1024.f);
    float rstd = rsqrtf(var + 1e-5f);

    float4 wv = *(const float4*)(lnw + c0);
    float wl[4] = { wv.x, wv.y, wv.z, wv.w };
    float n[4], mx = -3.4e38f;
#pragma unroll
    for (int k = 0; k < 4; k++) {
        n[k] = d[k] * rstd * wl[k];
        mx = fmaxf(mx, n[k]);
    }
    mx = blockMax(mx, sh);

    float e[4], es = 0.f;
#pragma unroll
    for (int k = 0; k < 4; k++) { e[k] = expf(n[k] - mx); es += e[k]; }
    float Z = blockSum(es, sh);

    float4 xv  = *(const float4*)(x + (size_t)row * CDIM + c0);
    float4 nzv = *(const float4*)(noise + (size_t)row * CDIM + c0);
    float xa[4] = { xv.x, xv.y, xv.z, xv.w };
    float nz[4] = { nzv.x, nzv.y, nzv.z, nzv.w };
    float o[4];
#pragma unroll
    for (int k = 0; k < 4; k++) {
        float p = e[k] / Z;
        float scaled = logf(LSf * p + 1.0f) / DENf;
        float comp = 1.0f - scaled;
        float scaling = (nz[k] >= comp) ? comp : comp - 1.0f;
        o[k] = xa[k] * (scaling + scaled);
    }
    *(float4*)(out + (size_t)row * CDIM + c0) = make_float4(o[0], o[1], o[2], o[3]);
}

// ---------------------------------------------------------------------------
extern "C" void kernel_launch(void* const* d_in, const int* in_sizes, int n_in,
                              void* d_out, int out_size) {
    const float* x     = (const float*)d_in[0];
    const float* w_qkv = (const float*)d_in[1];
    const float* ln_w  = (const float*)d_in[2];
    const float* noise = (const float*)d_in[3];
    float* out = (float*)d_out;

    const double e = 1.0 / (double)CDIM;
    const double ls = (1.0 + sqrt(1.0 - 4.0 * e) - 2.0 * e) / (2.0 * e * e);
    const float LSf = (float)ls;
    const float DENf = (float)log(ls);

    // One-time resources (created on the uncaptured correctness call; no device mem)
    static cudaStream_t s1 = nullptr, s2 = nullptr;
    static cudaEvent_t ev0 = nullptr, ev1 = nullptr, ev2 = nullptr, evQ = nullptr;
    if (s1 == nullptr) {
        cudaStreamCreateWithFlags(&s1, cudaStreamNonBlocking);
        cudaStreamCreateWithFlags(&s2, cudaStreamNonBlocking);
        cudaEventCreateWithFlags(&ev0, cudaEventDisableTiming);
        cudaEventCreateWithFlags(&ev1, cudaEventDisableTiming);
        cudaEventCreateWithFlags(&ev2, cudaEventDisableTiming);
        cudaEventCreateWithFlags(&evQ, cudaEventDisableTiming);
        const int gemm_smem_i = NSTAGE * STAGE_BYTES;
        cudaFuncSetAttribute(gemm_hmma, cudaFuncAttributeMaxDynamicSharedMemorySize, gemm_smem_i);
        cudaFuncSetAttribute(attn_hmma, cudaFuncAttributeMaxDynamicSharedMemorySize, ATTN_SMEM_BYTES);
    }
    const int gemm_smem = NSTAGE * STAGE_BYTES;   // 98304

    split_x<<<(BT * CDIM) / (256 * 4), 256>>>(x);
    split_wT<<<dim3(NQKV / 32, CDIM / 32), 256>>>(w_qkv);
    cudaEventRecord(ev0, 0);

    // K,V columns on stream 0 (bn tiles 8..23)
    gemm_hmma<<<dim3(16, BT / 128), 256, gemm_smem>>>(8);
    cudaEventRecord(ev1, 0);

    // Q columns on s2, concurrent with KV gemm (bn tiles 0..7)
    cudaStreamWaitEvent(s2, ev0, 0);
    gemm_hmma<<<dim3(8, BT / 128), 256, gemm_smem, s2>>>(0);
    cudaEventRecord(evQ, s2);

    // kv_outer + prefix on s1 after KV gemm
    cudaStreamWaitEvent(s1, ev1, 0);
    kv_outer<<<NBH * NCHUNK, 256, 0, s1>>>();
    prefix_G<<<NBH, 256, 0, s1>>>();
    cudaEventRecord(ev2, s1);

    // attn needs Q gemm + kv path
    cudaStreamWaitEvent(0, ev2, 0);
    cudaStreamWaitEvent(0, evQ, 0);
    attn_hmma<<<NBH * NCHUNK, 256, ATTN_SMEM_BYTES>>>();
    epilogue<<<BT, 256>>>(x, noise, ln_w, out, LSf, DENf);
}

// round 15
// speedup vs baseline: 1.1404x; 1.1404x over previous
#include <cuda_runtime.h>
#include <cuda_bf16.h>
#include <cuda_fp16.h>
#include <cstdint>
#include <cmath>

// Problem constants
#define NB    4
#define TSEQ  2048
#define CDIM  1024
#define NH    16
#define HS    64
#define BT    (NB*TSEQ)     // 8192 rows
#define NQKV  (3*CDIM)      // 3072
#define CHUNK 128
#define NCHUNK (TSEQ/CHUNK) // 16
#define NBH   (NB*NH)       // 64

// Scratch (device globals: allocation-free rule)
__device__ float g_qkv[(size_t)BT * NQKV];                 // 100.7 MB
__device__ float g_G[(size_t)NBH * NCHUNK * HS * HS];      // 16.8 MB
__device__ float g_Gp[(size_t)NBH * NCHUNK * HS * HS];     // 16.8 MB prefix sums
__device__ float g_logits[(size_t)BT * CDIM];              // 33.6 MB
__device__ __half g_Ah[2ULL * BT * CDIM];                  // 33.6 MB: x split, [t][row][k]
__device__ __half g_Bh[2ULL * NQKV * CDIM];                // 12.6 MB: (64*w) split, transposed [t][n][k]

// ======================= PTX helpers (base sm_80+ ISA only) =======================
__device__ __forceinline__ uint32_t smem_u32(const void* p) {
    uint32_t a;
    asm("{ .reg .u64 t; cvta.to.shared.u64 t, %1; cvt.u32.u64 %0, t; }" : "=r"(a) : "l"(p));
    return a;
}
#define CP_ASYNC16(dst, src) \
    asm volatile("cp.async.cg.shared.global [%0], [%1], 16;" :: "r"(dst), "l"(src) : "memory")
#define CP_COMMIT() asm volatile("cp.async.commit_group;" ::: "memory")
#define CP_WAIT(n)  asm volatile("cp.async.wait_group %0;" :: "n"(n) : "memory")

#define LDSM4(a0,a1,a2,a3,addr) \
    asm volatile("ldmatrix.sync.aligned.m8n8.x4.shared.b16 {%0,%1,%2,%3}, [%4];" \
                 : "=r"(a0),"=r"(a1),"=r"(a2),"=r"(a3) : "r"(addr))
#define LDSM2(b0,b1,addr) \
    asm volatile("ldmatrix.sync.aligned.m8n8.x2.shared.b16 {%0,%1}, [%2];" \
                 : "=r"(b0),"=r"(b1) : "r"(addr))
#define LDSM2T(b0,b1,addr) \
    asm volatile("ldmatrix.sync.aligned.m8n8.x2.trans.shared.b16 {%0,%1}, [%2];" \
                 : "=r"(b0),"=r"(b1) : "r"(addr))
#define MMA16816F16(d,a,b) \
    asm volatile("mma.sync.aligned.m16n8k16.row.col.f32.f16.f16.f32 " \
                 "{%0,%1,%2,%3},{%4,%5,%6,%7},{%8,%9},{%0,%1,%2,%3};" \
                 : "+f"((d)[0]),"+f"((d)[1]),"+f"((d)[2]),"+f"((d)[3]) \
                 : "r"((a)[0]),"r"((a)[1]),"r"((a)[2]),"r"((a)[3]),"r"((b)[0]),"r"((b)[1]))

// ======================= fp16 2-term split =======================
__device__ __forceinline__ void split2h(float v, unsigned short& u0, unsigned short& u1) {
    __half h0 = __float2half_rn(v);
    float r = v - __half2float(h0);
    __half h1 = __float2half_rn(r);
    u0 = __half_as_ushort(h0);
    u1 = __half_as_ushort(h1);
}
__device__ __forceinline__ uint32_t pack2(unsigned short lo, unsigned short hi) {
    return (uint32_t)lo | ((uint32_t)hi << 16);
}

// ======================= Kernel 0a: split x into 2 fp16 terms =======================
__global__ __launch_bounds__(256) void split_x(const float* __restrict__ in) {
    size_t i = ((size_t)blockIdx.x * 256 + threadIdx.x) * 4;
    float4 v = *(const float4*)(in + i);
    ushort4 o0, o1;
    split2h(v.x, o0.x, o1.x);
    split2h(v.y, o0.y, o1.y);
    split2h(v.z, o0.z, o1.z);
    split2h(v.w, o0.w, o1.w);
    unsigned short* p = (unsigned short*)g_Ah;
    const size_t S = (size_t)BT * CDIM;
    *(ushort4*)(p + i) = o0;
    *(ushort4*)(p + S + i) = o1;
}

// ======================= Kernel 0b: split + transpose (64*w_qkv) =======================
__global__ __launch_bounds__(256) void split_wT(const float* __restrict__ w) {
    __shared__ unsigned short t0[32][33], t1[32][33];
    const int n0 = blockIdx.x * 32, k0 = blockIdx.y * 32;
    const int tx = threadIdx.x & 31, ty = threadIdx.x >> 5;
#pragma unroll
    for (int j = 0; j < 4; j++) {
        int k = ty + j * 8;
        float v = w[(size_t)(k0 + k) * NQKV + n0 + tx] * 64.0f;
        split2h(v, t0[k][tx], t1[k][tx]);
    }
    __syncthreads();
    unsigned short* p = (unsigned short*)g_Bh;
    const size_t S = (size_t)NQKV * CDIM;
#pragma unroll
    for (int j = 0; j < 4; j++) {
        int n = ty + j * 8;
        size_t o = (size_t)(n0 + n) * CDIM + k0 + tx;
        p[o]     = t0[tx][n];
        p[S + o] = t1[tx][n];
    }
}

// ======================= Kernel 1: fused 3-pass HMMA GEMM (exact R13 body) =======================
// BK=32, unpadded XOR-swizzled tiles (8KB), 3-stage pipeline, 1 barrier/chunk.
#define BK 32
#define TILE_BYTES (128 * 64)                  // 8192 (128 rows x 64B)
#define STAGE_BYTES (4 * TILE_BYTES)           // 32768 (A0,A1,B0,B1)
#define NSTAGE 3
#define KCHUNKS (CDIM / BK)                    // 32

// swizzled byte offset of 16B chunk (row r, chunk c2 in 0..3) within a tile
__device__ __forceinline__ uint32_t swz(int r, int c2) {
    return (uint32_t)(r * 64 + ((c2 ^ ((r >> 1) & 3)) << 4));
}

__global__ __launch_bounds__(256, 2) void gemm_hmma(int bn0) {
    extern __shared__ __align__(16) unsigned char smem[];

    const int tid  = threadIdx.x;
    const int wid  = tid >> 5, lane = tid & 31;
    const int wm   = wid >> 2;
    const int wn   = wid & 3;
    const int bn   = bn0 + blockIdx.x, bm = blockIdx.y;

    const size_t SA = (size_t)BT * CDIM, SB = (size_t)NQKV * CDIM;
    const size_t arow0 = (size_t)(bm * 128) * CDIM;
    const size_t brow0 = (size_t)(bn * 128) * CDIM;

    const uint32_t sbase = smem_u32(smem);

    const int aR = lane & 15;                 // ldmatrix x4 row lane
    const int aCk = lane >> 4;                // ldmatrix x4 chunk sel (0/1)
    const int bR = lane & 7;                  // ldmatrix x2 row lane
    const int bCk = (lane >> 3) & 1;          // ldmatrix x2 chunk sel (0/1)

    float acc[4][4][4];
#pragma unroll
    for (int i = 0; i < 4; i++)
#pragma unroll
        for (int j = 0; j < 4; j++)
#pragma unroll
            for (int k = 0; k < 4; k++) acc[i][j][k] = 0.f;

    // gmem->smem: 512 chunks/tile; thread handles chunk ids tid and tid+256
    const int r0 = tid >> 2, c20 = tid & 3;   // rows 0..63
    const uint32_t so0 = swz(r0, c20);
    const uint32_t so1 = swz(r0 + 64, c20);
    const size_t go0 = (size_t)r0 * CDIM + c20 * 8;
    const size_t go1 = (size_t)(r0 + 64) * CDIM + c20 * 8;

    auto prefetch = [&](int chunk) {
        if (chunk < KCHUNKS) {
            const int s = chunk % NSTAGE;
            const size_t ko = (size_t)chunk * BK;
            const uint32_t st = sbase + s * STAGE_BYTES;
            const __half* A0 = g_Ah + arow0 + ko;
            const __half* B0 = g_Bh + brow0 + ko;
            CP_ASYNC16(st + so0,                  A0 + go0);
            CP_ASYNC16(st + so1,                  A0 + go1);
            CP_ASYNC16(st + TILE_BYTES + so0,     A0 + SA + go0);
            CP_ASYNC16(st + TILE_BYTES + so1,     A0 + SA + go1);
            CP_ASYNC16(st + 2 * TILE_BYTES + so0, B0 + go0);
            CP_ASYNC16(st + 2 * TILE_BYTES + so1, B0 + go1);
            CP_ASYNC16(st + 3 * TILE_BYTES + so0, B0 + SB + go0);
            CP_ASYNC16(st + 3 * TILE_BYTES + so1, B0 + SB + go1);
        }
        CP_COMMIT();
    };

    prefetch(0); prefetch(1);

    for (int i = 0; i < KCHUNKS; i++) {
        CP_WAIT(1);
        __syncthreads();
        // stage (i+2)%3 == (i-1)%3 : finished last iteration -> safe post-barrier
        prefetch(i + 2);

        const uint32_t st = sbase + (i % NSTAGE) * STAGE_BYTES;
        const uint32_t sA0 = st;
        const uint32_t sA1 = st + TILE_BYTES;
        const uint32_t sB0 = st + 2 * TILE_BYTES;
        const uint32_t sB1 = st + 3 * TILE_BYTES;

#pragma unroll
        for (int ks = 0; ks < 2; ks++) {
            const int kc = ks * 2;            // base chunk index (k0/8 = 0 or 2)
            uint32_t af[4][4], b0f[4][2], b1f[4][2];
#pragma unroll
            for (int mi = 0; mi < 4; mi++) {
                int r = wm * 64 + mi * 16 + aR;
                LDSM4(af[mi][0], af[mi][1], af[mi][2], af[mi][3], sA0 + swz(r, kc + aCk));
            }
#pragma unroll
            for (int nj = 0; nj < 4; nj++) {
                int r = wn * 32 + nj * 8 + bR;
                LDSM2(b0f[nj][0], b0f[nj][1], sB0 + swz(r, kc + bCk));
            }
            // a0 * b0
#pragma unroll
            for (int mi = 0; mi < 4; mi++)
#pragma unroll
                for (int nj = 0; nj < 4; nj++)
                    MMA16816F16(acc[mi][nj], af[mi], b0f[nj]);
            // a0 * b1
#pragma unroll
            for (int nj = 0; nj < 4; nj++) {
                int r = wn * 32 + nj * 8 + bR;
                LDSM2(b1f[nj][0], b1f[nj][1], sB1 + swz(r, kc + bCk));
            }
#pragma unroll
            for (int mi = 0; mi < 4; mi++)
#pragma unroll
                for (int nj = 0; nj < 4; nj++)
                    MMA16816F16(acc[mi][nj], af[mi], b1f[nj]);
            // a1 * b0 (reuse af registers)
#pragma unroll
            for (int mi = 0; mi < 4; mi++) {
                int r = wm * 64 + mi * 16 + aR;
                LDSM4(af[mi][0], af[mi][1], af[mi][2], af[mi][3], sA1 + swz(r, kc + aCk));
            }
#pragma unroll
            for (int mi = 0; mi < 4; mi++)
#pragma unroll
                for (int nj = 0; nj < 4; nj++)
                    MMA16816F16(acc[mi][nj], af[mi], b0f[nj]);
        }
    }

    const int g = lane >> 2, t2 = (lane & 3) * 2;
    const float inv64 = 0.015625f;
    float* Cb = g_qkv + (size_t)(bm * 128 + wm * 64) * NQKV + bn * 128 + wn * 32;
#pragma unroll
    for (int mi = 0; mi < 4; mi++) {
#pragma unroll
        for (int nj = 0; nj < 4; nj++) {
            float* p0 = Cb + (size_t)(mi * 16 + g) * NQKV + nj * 8 + t2;
            *(float2*)p0 = make_float2(acc[mi][nj][0] * inv64, acc[mi][nj][1] * inv64);
            *(float2*)(p0 + 8 * NQKV) = make_float2(acc[mi][nj][2] * inv64, acc[mi][nj][3] * inv64);
        }
    }
}

// ======================= Kernel 2: per-chunk K^T V (64x64, fp32, float4 loads) =======================
__global__ __launch_bounds__(256) void kv_outer() {
    const int bidx = blockIdx.x;
    const int bh = bidx >> 4, ci = bidx & 15;
    const int b = bh >> 4, h = bh & 15;
    const int t0 = ci * CHUNK;
    __shared__ float Ks[64][68];
    __shared__ float Vs[64][68];
    const int tid = threadIdx.x;
    const int ty = tid >> 4, tx = tid & 15;
    float acc[4][4] = {};
    const float* base = g_qkv + (size_t)(b * TSEQ + t0) * NQKV + h * HS;

    for (int half = 0; half < 2; half++) {
        __syncthreads();
        for (int idx = tid; idx < 64 * 16; idx += 256) {
            int r = idx >> 4, c4 = (idx & 15) * 4;
            const float* p = base + (size_t)(half * 64 + r) * NQKV + c4;
            *(float4*)&Ks[r][c4] = *(const float4*)(p + CDIM);
            *(float4*)&Vs[r][c4] = *(const float4*)(p + 2 * CDIM);
        }
        __syncthreads();
#pragma unroll 4
        for (int k = 0; k < 64; k++) {
            float rk[4], rv[4];
#pragma unroll
            for (int i = 0; i < 4; i++) rk[i] = Ks[k][i * 16 + ty];
#pragma unroll
            for (int j = 0; j < 4; j++) rv[j] = Vs[k][j * 16 + tx];
#pragma unroll
            for (int i = 0; i < 4; i++)
#pragma unroll
                for (int j = 0; j < 4; j++) acc[i][j] += rk[i] * rv[j];
        }
    }
    float* g = g_G + (size_t)bidx * (HS * HS);
#pragma unroll
    for (int i = 0; i < 4; i++)
#pragma unroll
        for (int j = 0; j < 4; j++)
            g[(i * 16 + ty) * HS + (j * 16 + tx)] = acc[i][j];
}

// ======================= Kernel 2b: prefix sums over G =======================
__global__ __launch_bounds__(256) void prefix_G() {
    const int bh = blockIdx.x;
    const float* Gb = g_G + (size_t)bh * NCHUNK * (HS * HS);
    float* Gp = g_Gp + (size_t)bh * NCHUNK * (HS * HS);
    for (int e = threadIdx.x * 4; e < HS * HS; e += 256 * 4) {
        float4 run = make_float4(0.f, 0.f, 0.f, 0.f);
#pragma unroll
        for (int j = 0; j < NCHUNK; j++) {
            *(float4*)(Gp + (size_t)j * (HS * HS) + e) = run;
            float4 gv = *(const float4*)(Gb + (size_t)j * (HS * HS) + e);
            run.x += gv.x; run.y += gv.y; run.z += gv.z; run.w += gv.w;
        }
    }
}

// ======================= Kernel 3: fused HMMA attention =======================
#define AST 72
#define SST 136
#define OFF_QH0 0
#define OFF_QH1 18432
#define OFF_KH0 36864
#define OFF_KH1 55296
#define OFF_VH0 73728
#define OFF_VH1 92160
#define OFF_MH0 110592
#define OFF_MH1 119808
#define OFF_SH0 129024
#define OFF_SH1 163840
#define ATTN_SMEM_BYTES 198656

__global__ __launch_bounds__(256) void attn_hmma() {
    extern __shared__ __align__(16) unsigned char sm[];
    const uint32_t sb = smem_u32(sm);

    const int bidx = blockIdx.x;
    const int bh = bidx >> 4, ci = bidx & 15;
    const int b = bh >> 4, h = bh & 15;
    const int tid = threadIdx.x, wid = tid >> 5, lane = tid & 31;
    const float* base = g_qkv + (size_t)(b * TSEQ + ci * CHUNK) * NQKV + h * HS;

    {
        unsigned short* QH0 = (unsigned short*)(sm + OFF_QH0);
        unsigned short* QH1 = (unsigned short*)(sm + OFF_QH1);
        unsigned short* KH0 = (unsigned short*)(sm + OFF_KH0);
        unsigned short* KH1 = (unsigned short*)(sm + OFF_KH1);
        unsigned short* VH0 = (unsigned short*)(sm + OFF_VH0);
        unsigned short* VH1 = (unsigned short*)(sm + OFF_VH1);
        for (int idx = tid; idx < 128 * 16; idx += 256) {
            int r = idx >> 4, c4 = (idx & 15) * 4;
            const float* p = base + (size_t)r * NQKV + c4;
            float4 q = *(const float4*)(p);
            float4 k = *(const float4*)(p + CDIM);
            float4 v = *(const float4*)(p + 2 * CDIM);
            int o = r * AST + c4;
            unsigned short a0, a1, b0, b1, e0, e1, f0, f1;
            split2h(q.x, a0, a1); split2h(q.y, b0, b1); split2h(q.z, e0, e1); split2h(q.w, f0, f1);
            *(uint2*)(QH0 + o) = make_uint2(pack2(a0, b0), pack2(e0, f0));
            *(uint2*)(QH1 + o) = make_uint2(pack2(a1, b1), pack2(e1, f1));
            split2h(k.x, a0, a1); split2h(k.y, b0, b1); split2h(k.z, e0, e1); split2h(k.w, f0, f1);
            *(uint2*)(KH0 + o) = make_uint2(pack2(a0, b0), pack2(e0, f0));
            *(uint2*)(KH1 + o) = make_uint2(pack2(a1, b1), pack2(e1, f1));
            split2h(v.x, a0, a1); split2h(v.y, b0, b1); split2h(v.z, e0, e1); split2h(v.w, f0, f1);
            *(uint2*)(VH0 + o) = make_uint2(pack2(a0, b0), pack2(e0, f0));
            *(uint2*)(VH1 + o) = make_uint2(pack2(a1, b1), pack2(e1, f1));
        }
        unsigned short* MH0 = (unsigned short*)(sm + OFF_MH0);
        unsigned short* MH1 = (unsigned short*)(sm + OFF_MH1);
        const float* Mp = g_Gp + ((size_t)bh * NCHUNK + ci) * (HS * HS);
        for (int idx = tid; idx < 64 * 16; idx += 256) {
            int r = idx >> 4, c4 = (idx & 15) * 4;
            float4 mv = *(const float4*)(Mp + r * HS + c4);
            unsigned short a0, a1, b0, b1, e0, e1, f0, f1;
            split2h(mv.x * 0.125f, a0, a1);
            split2h(mv.y * 0.125f, b0, b1);
            split2h(mv.z * 0.125f, e0, e1);
            split2h(mv.w * 0.125f, f0, f1);
            int o = r * AST + c4;
            *(uint2*)(MH0 + o) = make_uint2(pack2(a0, b0), pack2(e0, f0));
            *(uint2*)(MH1 + o) = make_uint2(pack2(a1, b1), pack2(e1, f1));
        }
    }
    __syncthreads();

    const int aR = lane & 15, aC = (lane >> 4) * 8;
    const int bR = lane & 7,  bC = ((lane >> 3) & 1) * 8;
    const int bRow = lane & 15;
    const int g = lane >> 2, t2 = (lane & 3) * 2;
    const int PA[3] = {0, 0, 1};
    const int PB[3] = {0, 1, 0};
    const uint32_t QHa[2] = { sb + OFF_QH0, sb + OFF_QH1 };
    const uint32_t KHa[2] = { sb + OFF_KH0, sb + OFF_KH1 };
    const uint32_t VHa[2] = { sb + OFF_VH0, sb + OFF_VH1 };
    const uint32_t MHa[2] = { sb + OFF_MH0, sb + OFF_MH1 };
    const uint32_t SHa[2] = { sb + OFF_SH0, sb + OFF_SH1 };

    // phase 1: S = Q K^T (128x128), warp tile 64x32
    {
        const int wm = wid >> 2, wn = wid & 3;
        float acc[4][4][4];
#pragma unroll
        for (int i = 0; i < 4; i++)
#pragma unroll
            for (int j = 0; j < 4; j++)
#pragma unroll
                for (int k = 0; k < 4; k++) acc[i][j][k] = 0.f;

#pragma unroll
        for (int p = 0; p < 3; p++) {
            const uint32_t Ap = QHa[PA[p]], Bp = KHa[PB[p]];
#pragma unroll
            for (int ks = 0; ks < 4; ks++) {
                const int k0 = ks * 16;
                uint32_t af[4][4], bf[4][2];
#pragma unroll
                for (int mi = 0; mi < 4; mi++)
                    LDSM4(af[mi][0], af[mi][1], af[mi][2], af[mi][3],
                          Ap + (uint32_t)((wm * 64 + mi * 16 + aR) * AST + k0 + aC) * 2);
#pragma unroll
                for (int nj = 0; nj < 4; nj++)
                    LDSM2(bf[nj][0], bf[nj][1],
                          Bp + (uint32_t)((wn * 32 + nj * 8 + bR) * AST + k0 + bC) * 2);
#pragma unroll
                for (int mi = 0; mi < 4; mi++)
#pragma unroll
                    for (int nj = 0; nj < 4; nj++)
                        MMA16816F16(acc[mi][nj], af[mi], bf[nj]);
            }
        }
        unsigned short* S0 = (unsigned short*)(sm + OFF_SH0);
        unsigned short* S1 = (unsigned short*)(sm + OFF_SH1);
#pragma unroll
        for (int mi = 0; mi < 4; mi++) {
#pragma unroll
            for (int nj = 0; nj < 4; nj++) {
                const int c0 = (wid & 3) * 32 + nj * 8 + t2;
#pragma unroll
                for (int hh = 0; hh < 2; hh++) {
                    const int r = (wid >> 2) * 64 + mi * 16 + g + hh * 8;
                    float va = (r >= c0)     ? acc[mi][nj][hh * 2]     * 0.125f : 0.f;
                    float vb = (r >= c0 + 1) ? acc[mi][nj][hh * 2 + 1] * 0.125f : 0.f;
                    unsigned short a0, a1, b0, b1;
                    split2h(va, a0, a1);
                    split2h(vb, b0, b1);
                    *(uint32_t*)(S0 + r * SST + c0) = pack2(a0, b0);
                    *(uint32_t*)(S1 + r * SST + c0) = pack2(a1, b1);
                }
            }
        }
    }
    __syncthreads();

    // phase 2: O = [S | Q] @ [V ; M'] (128x64, inner 192), warp tile 32x32
    {
        const int wy = wid >> 1, wx = wid & 1;
        float acc[2][4][4];
#pragma unroll
        for (int i = 0; i < 2; i++)
#pragma unroll
            for (int j = 0; j < 4; j++)
#pragma unroll
                for (int k = 0; k < 4; k++) acc[i][j][k] = 0.f;

#pragma unroll
        for (int p = 0; p < 3; p++) {
            const uint32_t Sa = SHa[PA[p]], Qa = QHa[PA[p]];
            const uint32_t Va = VHa[PB[p]], Ma = MHa[PB[p]];
#pragma unroll
            for (int step = 0; step < 12; step++) {
                const int k0 = step * 16;
                uint32_t af[2][4], bf[4][2];
#pragma unroll
                for (int mi = 0; mi < 2; mi++) {
                    const int row = wy * 32 + mi * 16 + aR;
                    uint32_t addr = (k0 < 128)
                        ? Sa + (uint32_t)(row * SST + k0 + aC) * 2
                        : Qa + (uint32_t)(row * AST + (k0 - 128) + aC) * 2;
                    LDSM4(af[mi][0], af[mi][1], af[mi][2], af[mi][3], addr);
                }
#pragma unroll
                for (int nj = 0; nj < 4; nj++) {
                    const int n0 = wx * 32 + nj * 8;
                    uint32_t addr = (k0 < 128)
                        ? Va + (uint32_t)((k0 + bRow) * AST + n0) * 2
                        : Ma + (uint32_t)((k0 - 128 + bRow) * AST + n0) * 2;
                    LDSM2T(bf[nj][0], bf[nj][1], addr);
                }
#pragma unroll
                for (int mi = 0; mi < 2; mi++)
#pragma unroll
                    for (int nj = 0; nj < 4; nj++)
                        MMA16816F16(acc[mi][nj], af[mi], bf[nj]);
            }
        }
        float* outp = g_logits + (size_t)(b * TSEQ + ci * CHUNK) * CDIM + h * HS;
#pragma unroll
        for (int mi = 0; mi < 2; mi++) {
#pragma unroll
            for (int nj = 0; nj < 4; nj++) {
                const int r = wy * 32 + mi * 16 + g;
                const int c = wx * 32 + nj * 8 + t2;
                *(float2*)(outp + (size_t)r * CDIM + c) =
                    make_float2(acc[mi][nj][0], acc[mi][nj][1]);
                *(float2*)(outp + (size_t)(r + 8) * CDIM + c) =
                    make_float2(acc[mi][nj][2], acc[mi][nj][3]);
            }
        }
    }
}

// ======================= Kernel 4: fused epilogue (float4) =======================
__device__ __forceinline__ float warpSum(float v) {
#pragma unroll
    for (int o = 16; o; o >>= 1) v += __shfl_xor_sync(0xffffffffu, v, o);
    return v;
}
__device__ __forceinline__ float warpMax(float v) {
#pragma unroll
    for (int o = 16; o; o >>= 1) v = fmaxf(v, __shfl_xor_sync(0xffffffffu, v, o));
    return v;
}
__device__ float blockSum(float v, float* sh) {
    int lane = threadIdx.x & 31, w = threadIdx.x >> 5;
    v = warpSum(v);
    if (lane == 0) sh[w] = v;
    __syncthreads();
    if (w == 0) {
        float t = (lane < 8) ? sh[lane] : 0.f;
        t = warpSum(t);
        if (lane == 0) sh[32] = t;
    }
    __syncthreads();
    float r = sh[32];
    __syncthreads();
    return r;
}
__device__ float blockMax(float v, float* sh) {
    int lane = threadIdx.x & 31, w = threadIdx.x >> 5;
    v = warpMax(v);
    if (lane == 0) sh[w] = v;
    __syncthreads();
    if (w == 0) {
        float t = (lane < 8) ? sh[lane] : -3.4e38f;
        t = warpMax(t);
        if (lane == 0) sh[32] = t;
    }
    __syncthreads();
    float r = sh[32];
    __syncthreads();
    return r;
}

__global__ __launch_bounds__(256) void epilogue(const float* __restrict__ x,
                                                const float* __restrict__ noise,
                                                const float* __restrict__ lnw,
                                                float* __restrict__ out,
                                                float LSf, float DENf) {
    __shared__ float sh[33];
    const int row = blockIdx.x;
    const int tid = threadIdx.x;
    const int c0 = tid * 4;
    const float* L = g_logits + (size_t)row * CDIM;

    float4 lv = *(const float4*)(L + c0);
    float l[4] = { lv.x, lv.y, lv.z, lv.w };

    float s = (l[0] + l[1]) + (l[2] + l[3]);
    float mu = blockSum(s, sh) * (1.f / 1024.f);

    float d[4], sq = 0.f;
#pragma unroll
    for (int k = 0; k < 4; k++) { d[k] = l[k] - mu; sq += d[k] * d[k]; }
    float var = blockSum(sq, sh) * (1.f / 1024.f);
    float rstd = rsqrtf(var + 1e-5f);

    float4 wv = *(const float4*)(lnw + c0);
    float wl[4] = { wv.x, wv.y, wv.z, wv.w };
    float n[4], mx = -3.4e38f;
#pragma unroll
    for (int k = 0; k < 4; k++) {
        n[k] = d[k] * rstd * wl[k];
        mx = fmaxf(mx, n[k]);
    }
    mx = blockMax(mx, sh);

    float e[4], es = 0.f;
#pragma unroll
    for (int k = 0; k < 4; k++) { e[k] = expf(n[k] - mx); es += e[k]; }
    float Z = blockSum(es, sh);

    float4 xv  = *(const float4*)(x + (size_t)row * CDIM + c0);
    float4 nzv = *(const float4*)(noise + (size_t)row * CDIM + c0);
    float xa[4] = { xv.x, xv.y, xv.z, xv.w };
    float nz[4] = { nzv.x, nzv.y, nzv.z, nzv.w };
    float o[4];
#pragma unroll
    for (int k = 0; k < 4; k++) {
        float p = e[k] / Z;
        float scaled = logf(LSf * p + 1.0f) / DENf;
        float comp = 1.0f - scaled;
        float scaling = (nz[k] >= comp) ? comp : comp - 1.0f;
        o[k] = xa[k] * (scaling + scaled);
    }
    *(float4*)(out + (size_t)row * CDIM + c0) = make_float4(o[0], o[1], o[2], o[3]);
}

// ---------------------------------------------------------------------------
extern "C" void kernel_launch(void* const* d_in, const int* in_sizes, int n_in,
                              void* d_out, int out_size) {
    const float* x     = (const float*)d_in[0];
    const float* w_qkv = (const float*)d_in[1];
    const float* ln_w  = (const float*)d_in[2];
    const float* noise = (const float*)d_in[3];
    float* out = (float*)d_out;

    const double e = 1.0 / (double)CDIM;
    const double ls = (1.0 + sqrt(1.0 - 4.0 * e) - 2.0 * e) / (2.0 * e * e);
    const float LSf = (float)ls;
    const float DENf = (float)log(ls);

    // One-time resources (created on the uncaptured correctness call; no device mem)
    static cudaStream_t s1 = nullptr, s2 = nullptr;
    static cudaEvent_t ev0 = nullptr, ev1 = nullptr, ev2 = nullptr, evQ = nullptr;
    if (s1 == nullptr) {
        cudaStreamCreateWithFlags(&s1, cudaStreamNonBlocking);
        cudaStreamCreateWithFlags(&s2, cudaStreamNonBlocking);
        cudaEventCreateWithFlags(&ev0, cudaEventDisableTiming);
        cudaEventCreateWithFlags(&ev1, cudaEventDisableTiming);
        cudaEventCreateWithFlags(&ev2, cudaEventDisableTiming);
        cudaEventCreateWithFlags(&evQ, cudaEventDisableTiming);
        const int gemm_smem_i = NSTAGE * STAGE_BYTES;
        cudaFuncSetAttribute(gemm_hmma, cudaFuncAttributeMaxDynamicSharedMemorySize, gemm_smem_i);
        cudaFuncSetAttribute(attn_hmma, cudaFuncAttributeMaxDynamicSharedMemorySize, ATTN_SMEM_BYTES);
    }
    const int gemm_smem = NSTAGE * STAGE_BYTES;   // 98304

    split_x<<<(BT * CDIM) / (256 * 4), 256>>>(x);
    split_wT<<<dim3(NQKV / 32, CDIM / 32), 256>>>(w_qkv);
    cudaEventRecord(ev0, 0);

    // K,V columns on stream 0 (bn tiles 8..23)
    gemm_hmma<<<dim3(16, BT / 128), 256, gemm_smem>>>(8);
    cudaEventRecord(ev1, 0);

    // Q columns on s2, concurrent with KV gemm (bn tiles 0..7)
    cudaStreamWaitEvent(s2, ev0, 0);
    gemm_hmma<<<dim3(8, BT / 128), 256, gemm_smem, s2>>>(0);
    cudaEventRecord(evQ, s2);

    // kv_outer + prefix on s1 after KV gemm
    cudaStreamWaitEvent(s1, ev1, 0);
    kv_outer<<<NBH * NCHUNK, 256, 0, s1>>>();
    prefix_G<<<NBH, 256, 0, s1>>>();
    cudaEventRecord(ev2, s1);

    // attn needs Q gemm + kv path
    cudaStreamWaitEvent(0, ev2, 0);
    cudaStreamWaitEvent(0, evQ, 0);
    attn_hmma<<<NBH * NCHUNK, 256, ATTN_SMEM_BYTES>>>();
    epilogue<<<BT, 256>>>(x, noise, ln_w, out, LSf, DENf);
}